// round 1
// baseline (speedup 1.0000x reference)
#include <cuda_runtime.h>
#include <math_constants.h>

#define NHEADS 16
#define DH     64
#define ODIM   1024
#define NB     2
#define NLQ    2048
#define NLK    2048
#define BIGF   1e10f

// Scratch for projected Q/K/V (allowed: __device__ globals, no runtime alloc)
__device__ float g_QW[NB * NLQ * ODIM];
__device__ float g_KW[NB * NLK * ODIM];
__device__ float g_VW[NB * NLK * ODIM];

// ---------------------------------------------------------------------------
// Projection GEMM: C[M,N] = X[M,K] @ W[N,K]^T   (M=4096, N=K=1024)
// 64x64 tile, BK=16, 256 threads, 4x4 microtile per thread.
// ---------------------------------------------------------------------------
__global__ __launch_bounds__(256) void proj_gemm_kernel(
    const float* __restrict__ X, const float* __restrict__ W,
    float* __restrict__ C)
{
    constexpr int K = ODIM;
    constexpr int N = ODIM;
    __shared__ float As[16][64];   // [k][m]
    __shared__ float Bs[16][64];   // [k][n]

    const int tid = threadIdx.x;
    const int ty  = tid >> 4;      // 0..15 -> 4 rows
    const int tx  = tid & 15;      // 0..15 -> 4 cols
    const int m0  = blockIdx.y * 64;
    const int n0  = blockIdx.x * 64;

    const int lr = tid >> 2;          // 0..63 tile row
    const int lc = (tid & 3) * 4;     // 0,4,8,12 within BK
    const float* Xp = X + (size_t)(m0 + lr) * K + lc;
    const float* Wp = W + (size_t)(n0 + lr) * K + lc;

    float acc[4][4] = {};

    for (int k0 = 0; k0 < K; k0 += 16) {
        float4 a4 = *(const float4*)(Xp + k0);
        float4 b4 = *(const float4*)(Wp + k0);
        As[lc + 0][lr] = a4.x; As[lc + 1][lr] = a4.y;
        As[lc + 2][lr] = a4.z; As[lc + 3][lr] = a4.w;
        Bs[lc + 0][lr] = b4.x; Bs[lc + 1][lr] = b4.y;
        Bs[lc + 2][lr] = b4.z; Bs[lc + 3][lr] = b4.w;
        __syncthreads();

        #pragma unroll
        for (int kk = 0; kk < 16; kk++) {
            float4 av = *(const float4*)&As[kk][ty * 4];
            float4 bv = *(const float4*)&Bs[kk][tx * 4];
            float a[4] = {av.x, av.y, av.z, av.w};
            float b[4] = {bv.x, bv.y, bv.z, bv.w};
            #pragma unroll
            for (int i = 0; i < 4; i++)
                #pragma unroll
                for (int j = 0; j < 4; j++)
                    acc[i][j] = fmaf(a[i], b[j], acc[i][j]);
        }
        __syncthreads();
    }

    #pragma unroll
    for (int i = 0; i < 4; i++) {
        float4 o = make_float4(acc[i][0], acc[i][1], acc[i][2], acc[i][3]);
        *(float4*)&C[(size_t)(m0 + ty * 4 + i) * N + n0 + tx * 4] = o;
    }
}

// ---------------------------------------------------------------------------
// Flash-style attention over projected tensors.
// One CTA = 64 q-rows of one (batch, head). Loops over all 32 k-tiles of 64
// (NO tile skipping: the "tril incl. diagonal" penalty means degenerate rows
// average over keys tied at exactly -1e10; fp32 arithmetic here reproduces the
// reference's tie semantics so processing all tiles is exact).
// smem: Qs [d][q], KPs = Ks [d][k] reused as Ps [k][q], Vs [k][d] = 48 KB.
// ---------------------------------------------------------------------------
__global__ __launch_bounds__(256) void attn_kernel(
    const float* __restrict__ v_mask, const float* __restrict__ q_mask,
    float* __restrict__ out)
{
    __shared__ float Qs[64 * 64];   // [d][q]
    __shared__ float KPs[64 * 64];  // Ks as [d][k], then Ps as [k][q]
    __shared__ float Vs[64 * 64];   // [k][d]

    const int tid = threadIdx.x;
    const int ty  = tid >> 4;       // 0..15  -> q rows ty*4..+3
    const int tx  = tid & 15;       // 0..15  -> cols tx*4..+3
    const int q0  = blockIdx.x * 64;
    const int h   = blockIdx.y;
    const int b   = blockIdx.z;

    const float* QW = g_QW + (size_t)b * NLQ * ODIM + h * DH;
    const float* KW = g_KW + (size_t)b * NLK * ODIM + h * DH;
    const float* VW = g_VW + (size_t)b * NLK * ODIM + h * DH;
    const float* vm = v_mask + (size_t)b * NLK;

    const int lr = tid >> 2;          // 0..63 tile row for loads
    const int cb = (tid & 3) * 16;    // column base (4 float4s per thread)

    // Load Q tile transposed: Qs[d][q]
    #pragma unroll
    for (int u = 0; u < 4; u++) {
        int c = cb + u * 4;
        float4 v4 = *(const float4*)&QW[(size_t)(q0 + lr) * ODIM + c];
        Qs[(c + 0) * 64 + lr] = v4.x;
        Qs[(c + 1) * 64 + lr] = v4.y;
        Qs[(c + 2) * 64 + lr] = v4.z;
        Qs[(c + 3) * 64 + lr] = v4.w;
    }

    float o[4][4] = {};
    float mrow[4] = {-CUDART_INF_F, -CUDART_INF_F, -CUDART_INF_F, -CUDART_INF_F};
    float lrow[4] = {};

    for (int kt = 0; kt < NLK / 64; kt++) {
        const int k0 = kt * 64;
        __syncthreads();   // previous iteration's reads of KPs/Vs complete

        // Load K tile transposed (Ks[d][k]) and V tile direct (Vs[k][d])
        #pragma unroll
        for (int u = 0; u < 4; u++) {
            int c = cb + u * 4;
            float4 kv = *(const float4*)&KW[(size_t)(k0 + lr) * ODIM + c];
            KPs[(c + 0) * 64 + lr] = kv.x;
            KPs[(c + 1) * 64 + lr] = kv.y;
            KPs[(c + 2) * 64 + lr] = kv.z;
            KPs[(c + 3) * 64 + lr] = kv.w;
            float4 vv = *(const float4*)&VW[(size_t)(k0 + lr) * ODIM + c];
            *(float4*)&Vs[lr * 64 + c] = vv;
        }
        __syncthreads();

        // S = Q @ K^T for this tile (4x4 fragment per thread)
        float s[4][4] = {};
        #pragma unroll 8
        for (int d = 0; d < 64; d++) {
            float4 av = *(const float4*)&Qs[d * 64 + ty * 4];
            float4 bv = *(const float4*)&KPs[d * 64 + tx * 4];
            float a[4] = {av.x, av.y, av.z, av.w};
            float bb[4] = {bv.x, bv.y, bv.z, bv.w};
            #pragma unroll
            for (int i = 0; i < 4; i++)
                #pragma unroll
                for (int j = 0; j < 4; j++)
                    s[i][j] = fmaf(a[i], bb[j], s[i][j]);
        }

        // scale + masks (fp32 arithmetic identical in structure to reference)
        float vmv[4];
        #pragma unroll
        for (int j = 0; j < 4; j++) vmv[j] = vm[k0 + tx * 4 + j];
        #pragma unroll
        for (int i = 0; i < 4; i++) {
            const int qg = q0 + ty * 4 + i;
            #pragma unroll
            for (int j = 0; j < 4; j++) {
                const int kg = k0 + tx * 4 + j;
                float x = s[i][j] * 0.125f;           // 1/sqrt(64)
                x -= (1.0f - vmv[j]) * BIGF;          // key padding
                if (kg <= qg) x -= BIGF;              // tril incl. diagonal
                s[i][j] = x;
            }
        }

        // Online softmax update (row stats shared across the 16 tx lanes)
        #pragma unroll
        for (int i = 0; i < 4; i++) {
            float rm = fmaxf(fmaxf(s[i][0], s[i][1]), fmaxf(s[i][2], s[i][3]));
            rm = fmaxf(rm, __shfl_xor_sync(0xffffffffu, rm, 1));
            rm = fmaxf(rm, __shfl_xor_sync(0xffffffffu, rm, 2));
            rm = fmaxf(rm, __shfl_xor_sync(0xffffffffu, rm, 4));
            rm = fmaxf(rm, __shfl_xor_sync(0xffffffffu, rm, 8));
            const float mnew = fmaxf(mrow[i], rm);
            const float sc = __expf(mrow[i] - mnew);   // exp(-inf)=0 first pass
            mrow[i] = mnew;
            float rs = 0.f;
            #pragma unroll
            for (int j = 0; j < 4; j++) {
                s[i][j] = __expf(s[i][j] - mnew);
                rs += s[i][j];
            }
            rs += __shfl_xor_sync(0xffffffffu, rs, 1);
            rs += __shfl_xor_sync(0xffffffffu, rs, 2);
            rs += __shfl_xor_sync(0xffffffffu, rs, 4);
            rs += __shfl_xor_sync(0xffffffffu, rs, 8);
            lrow[i] = lrow[i] * sc + rs;
            #pragma unroll
            for (int j = 0; j < 4; j++) o[i][j] *= sc;
        }

        __syncthreads();   // all Ks reads done before P overwrites the buffer

        // Write P into KPs as [k][q]
        #pragma unroll
        for (int i = 0; i < 4; i++)
            #pragma unroll
            for (int j = 0; j < 4; j++)
                KPs[(tx * 4 + j) * 64 + (ty * 4 + i)] = s[i][j];
        __syncthreads();

        // O += P @ V
        #pragma unroll 8
        for (int kk = 0; kk < 64; kk++) {
            float4 av = *(const float4*)&KPs[kk * 64 + ty * 4];
            float4 bv = *(const float4*)&Vs[kk * 64 + tx * 4];
            float a[4] = {av.x, av.y, av.z, av.w};
            float bb[4] = {bv.x, bv.y, bv.z, bv.w};
            #pragma unroll
            for (int i = 0; i < 4; i++)
                #pragma unroll
                for (int j = 0; j < 4; j++)
                    o[i][j] = fmaf(a[i], bb[j], o[i][j]);
        }
    }

    // Epilogue: normalize, apply q_mask, store
    #pragma unroll
    for (int i = 0; i < 4; i++) {
        const int qg = q0 + ty * 4 + i;
        const float qm = q_mask[(size_t)b * NLQ + qg];
        const float inv = qm / lrow[i];
        float4 r = make_float4(o[i][0] * inv, o[i][1] * inv,
                               o[i][2] * inv, o[i][3] * inv);
        *(float4*)&out[((size_t)b * NLQ + qg) * ODIM + h * DH + tx * 4] = r;
    }
}

// ---------------------------------------------------------------------------
extern "C" void kernel_launch(void* const* d_in, const int* in_sizes, int n_in,
                              void* d_out, int out_size)
{
    const float* q     = (const float*)d_in[0];
    const float* k     = (const float*)d_in[1];
    const float* v     = (const float*)d_in[2];
    const float* vmask = (const float*)d_in[3];
    const float* qmask = (const float*)d_in[4];
    const float* Wq    = (const float*)d_in[5];
    const float* Wk    = (const float*)d_in[6];
    const float* Wv    = (const float*)d_in[7];
    float* out = (float*)d_out;

    float *qw, *kw, *vw;
    cudaGetSymbolAddress((void**)&qw, g_QW);
    cudaGetSymbolAddress((void**)&kw, g_KW);
    cudaGetSymbolAddress((void**)&vw, g_VW);

    dim3 pg(ODIM / 64, (NB * NLQ) / 64);
    proj_gemm_kernel<<<pg, 256>>>(q, Wq, qw);
    proj_gemm_kernel<<<pg, 256>>>(k, Wk, kw);
    proj_gemm_kernel<<<pg, 256>>>(v, Wv, vw);

    attn_kernel<<<dim3(NLQ / 64, NHEADS, NB), 256>>>(vmask, qmask, out);
}